// round 1
// baseline (speedup 1.0000x reference)
#include <cuda_runtime.h>
#include <cuda_bf16.h>
#include <math.h>

// Problem constants
#define BB 16
#define NN 2048
#define CC 64
#define KK 20

// ---------------- device scratch (no runtime alloc allowed) ----------------
__device__ float g_sq[BB * NN];                 // |x|^2 per point
__device__ float g_u[BB * NN * CC];             // xi@(W1a-W1b)+b1
__device__ float g_v[BB * NN * CC];             // xj@W1b
__device__ float g_dist[BB * NN * NN];          // 268MB pairwise distances
__device__ int   g_idx[BB * NN * KK];           // knn indices (global rows)
__device__ float g_agg[BB * NN * CC];           // max over k of MLP
__device__ float g_y[BB * CC];                  // SE gate
__device__ float g_avg[BB * NN];
__device__ float g_mx[BB * NN];

// ---------------- K0: per-point prep: sq, u, v ----------------
// 4 points per block, 256 threads
__global__ void __launch_bounds__(256) k_prep(const float* __restrict__ x,
                                              const float* __restrict__ W1,
                                              const float* __restrict__ b1) {
    __shared__ float sW[128 * 64];   // 32KB
    __shared__ float sx[4 * 64];
    __shared__ float sred[4 * 64];
    int t = threadIdx.x;
    for (int i = t; i < 128 * 64; i += 256) sW[i] = W1[i];
    int p0 = blockIdx.x * 4;
    for (int i = t; i < 4 * 64; i += 256) sx[i] = x[p0 * 64 + i];
    __syncthreads();
    int p = t >> 6, c = t & 63;
    const float* xv = &sx[p * 64];
    float ua = 0.f, va = 0.f;
#pragma unroll 8
    for (int k = 0; k < 64; k++) {
        float xk = xv[k];
        ua += xk * sW[k * 64 + c];
        va += xk * sW[(64 + k) * 64 + c];
    }
    int row = p0 + p;
    g_u[row * 64 + c] = ua - va + b1[c];
    g_v[row * 64 + c] = va;
    sred[t] = xv[c] * xv[c];
    __syncthreads();
    if (c == 0) {
        float s = 0.f;
        for (int k = 0; k < 64; k++) s += sred[p * 64 + k];
        g_sq[row] = s;
    }
}

// ---------------- K1a: pairwise distance GEMM ----------------
// grid (jt=16, it=16, b=16), 256 threads, 128x128 tile, 8x8 per thread
extern __shared__ float dsm[];
__global__ void __launch_bounds__(256) k_dist(const float* __restrict__ x) {
    float* As = dsm;            // [64][129] layout k-major, padded
    float* Bs = dsm + 8256;
    float* sqi = dsm + 16512;   // 128
    float* sqj = dsm + 16640;   // 128
    int t = threadIdx.x;
    int bz = blockIdx.z;
    int it = blockIdx.y, jt = blockIdx.x;
    int base_i = (bz << 11) + it * 128;
    int base_j = (bz << 11) + jt * 128;

    for (int idx = t; idx < 8192; idx += 256) {
        int r = idx >> 6, c = idx & 63;
        As[c * 129 + r] = x[(base_i + r) * 64 + c];
        Bs[c * 129 + r] = x[(base_j + r) * 64 + c];
    }
    if (t < 128) sqi[t] = g_sq[base_i + t];
    else         sqj[t - 128] = g_sq[base_j + t - 128];
    __syncthreads();

    int tx = t & 15, ty = t >> 4;
    float acc[8][8];
#pragma unroll
    for (int r = 0; r < 8; r++)
#pragma unroll
        for (int s = 0; s < 8; s++) acc[r][s] = 0.f;

#pragma unroll 4
    for (int k = 0; k < 64; k++) {
        float a[8], b[8];
#pragma unroll
        for (int r = 0; r < 8; r++) a[r] = As[k * 129 + ty + r * 16];
#pragma unroll
        for (int s = 0; s < 8; s++) b[s] = Bs[k * 129 + tx + s * 16];
#pragma unroll
        for (int r = 0; r < 8; r++)
#pragma unroll
            for (int s = 0; s < 8; s++) acc[r][s] += a[r] * b[s];
    }

#pragma unroll
    for (int r = 0; r < 8; r++) {
        int il = ty + r * 16;
        float sa = sqi[il];
        size_t rowbase = (size_t)(base_i + il) * 2048 + (size_t)jt * 128;
#pragma unroll
        for (int s = 0; s < 8; s++) {
            int jl = tx + s * 16;
            g_dist[rowbase + jl] = sa + sqj[jl] - 2.f * acc[r][s];
        }
    }
}

// ---------------- K1b: top-K=20 smallest per row (tie -> lower index) ----------------
__global__ void __launch_bounds__(256) k_topk() {
    __shared__ float sd[2048];
    __shared__ float bv[8];
    __shared__ int   bi[8];
    int row = blockIdx.x;
    int t = threadIdx.x;
    int b = row >> 11;
    const float* dr = &g_dist[(size_t)row * 2048];
    for (int j = t; j < 2048; j += 256) sd[j] = dr[j];
    __syncthreads();
    int lane = t & 31, w = t >> 5;
    for (int sel = 0; sel < 20; sel++) {
        float mv = 3.4e38f; int mi = 0x7fffffff;
        for (int j = t; j < 2048; j += 256) {
            float v = sd[j];
            if (v < mv) { mv = v; mi = j; }
        }
#pragma unroll
        for (int o = 16; o; o >>= 1) {
            float ov = __shfl_down_sync(0xffffffffu, mv, o);
            int   oi = __shfl_down_sync(0xffffffffu, mi, o);
            if (ov < mv || (ov == mv && oi < mi)) { mv = ov; mi = oi; }
        }
        if (!lane) { bv[w] = mv; bi[w] = mi; }
        __syncthreads();
        if (!t) {
            float best = bv[0]; int bx = bi[0];
            for (int q = 1; q < 8; q++)
                if (bv[q] < best || (bv[q] == best && bi[q] < bx)) { best = bv[q]; bx = bi[q]; }
            sd[bx] = 3.4e38f;
            g_idx[row * 20 + sel] = (b << 11) + bx;
        }
        __syncthreads();
    }
}

// ---------------- K2: edge MLP (layers 2,3) + max over k ----------------
// 16 points/block (320 edges), 256 threads, per-thread 10x8 tile
#define EP 321
extern __shared__ float esm[];
__global__ void __launch_bounds__(256) k_edge(const float* __restrict__ W2,
                                              const float* __restrict__ b2,
                                              const float* __restrict__ W3,
                                              const float* __restrict__ b3) {
    float* H1T = esm;                 // [64][EP]
    float* H2T = esm + 64 * EP;       // [64][EP]
    float* W2r = esm + 2 * 64 * EP;   // 4096 rearranged [k][tn][s]
    float* W3r = W2r + 4096;
    float* su  = W3r + 4096;          // 16*64
    float* b2s = su + 1024;
    float* b3s = b2s + 64;
    int*  sidx = (int*)(b3s + 64);    // 320

    int t = threadIdx.x;
    int base = blockIdx.x * 16;       // global point row base

    for (int idx = t; idx < 4096; idx += 256) {
        int k = idx >> 6, rem = idx & 63, tn = rem >> 3, s = rem & 7;
        W2r[idx] = W2[k * 64 + tn + s * 8];
        W3r[idx] = W3[k * 64 + tn + s * 8];
    }
    for (int idx = t; idx < 1024; idx += 256) su[idx] = g_u[base * 64 + idx];
    if (t < 64) { b2s[t] = b2[t]; b3s[t] = b3[t]; }
    for (int idx = t; idx < 320; idx += 256) sidx[idx] = g_idx[base * 20 + idx];
    __syncthreads();

    // build H1 = relu(u_i + v_j), transposed [c][e]
    for (int idx = t; idx < 20480; idx += 256) {
        int e = idx >> 6, c = idx & 63;
        int nbr = sidx[e];
        float val = su[(e / 20) * 64 + c] + g_v[nbr * 64 + c];
        H1T[c * EP + e] = fmaxf(val, 0.f);
    }
    __syncthreads();

    int tm = t & 31, tn = t >> 5;
    float acc[10][8];
#pragma unroll
    for (int r = 0; r < 10; r++)
#pragma unroll
        for (int s = 0; s < 8; s++) acc[r][s] = 0.f;

    // GEMM1: H2 = relu(H1 @ W2 + b2)
#pragma unroll 2
    for (int k = 0; k < 64; k++) {
        float a[10];
#pragma unroll
        for (int r = 0; r < 10; r++) a[r] = H1T[k * EP + tm + r * 32];
        float4 bl = *(const float4*)&W2r[(k * 8 + tn) * 8];
        float4 bh = *(const float4*)&W2r[(k * 8 + tn) * 8 + 4];
        float bb[8] = {bl.x, bl.y, bl.z, bl.w, bh.x, bh.y, bh.z, bh.w};
#pragma unroll
        for (int r = 0; r < 10; r++)
#pragma unroll
            for (int s = 0; s < 8; s++) acc[r][s] += a[r] * bb[s];
    }
#pragma unroll
    for (int s = 0; s < 8; s++) {
        int n = tn + s * 8;
        float bias = b2s[n];
#pragma unroll
        for (int r = 0; r < 10; r++)
            H2T[n * EP + tm + r * 32] = fmaxf(acc[r][s] + bias, 0.f);
    }
    __syncthreads();

    // GEMM2: H3 = H2 @ W3 + b3  (into H1T buffer)
#pragma unroll
    for (int r = 0; r < 10; r++)
#pragma unroll
        for (int s = 0; s < 8; s++) acc[r][s] = 0.f;
#pragma unroll 2
    for (int k = 0; k < 64; k++) {
        float a[10];
#pragma unroll
        for (int r = 0; r < 10; r++) a[r] = H2T[k * EP + tm + r * 32];
        float4 bl = *(const float4*)&W3r[(k * 8 + tn) * 8];
        float4 bh = *(const float4*)&W3r[(k * 8 + tn) * 8 + 4];
        float bb[8] = {bl.x, bl.y, bl.z, bl.w, bh.x, bh.y, bh.z, bh.w};
#pragma unroll
        for (int r = 0; r < 10; r++)
#pragma unroll
            for (int s = 0; s < 8; s++) acc[r][s] += a[r] * bb[s];
    }
    float* H3T = H1T;  // safe: H1T last read before previous sync
#pragma unroll
    for (int s = 0; s < 8; s++) {
        int n = tn + s * 8;
        float bias = b3s[n];
#pragma unroll
        for (int r = 0; r < 10; r++)
            H3T[n * EP + tm + r * 32] = acc[r][s] + bias;
    }
    __syncthreads();

    // max over K=20 per point
    for (int idx = t; idx < 1024; idx += 256) {
        int p = idx >> 6, n = idx & 63;
        const float* hp = &H3T[n * EP + p * 20];
        float m = hp[0];
#pragma unroll
        for (int kk = 1; kk < 20; kk++) m = fmaxf(m, hp[kk]);
        g_agg[(base + p) * 64 + n] = m;
    }
}

// ---------------- K3: SE gate: s=mean(agg), y=sigmoid(relu(s@w1)@w2) ----------------
__global__ void __launch_bounds__(256) k_se(const float* __restrict__ se_w1,
                                            const float* __restrict__ se_w2) {
    int b = blockIdx.x, t = threadIdx.x;
    __shared__ float red[256];
    __shared__ float ss[64];
    __shared__ float rr[4];
    int c = t & 63, g = t >> 6;
    float acc = 0.f;
    for (int r = g; r < 2048; r += 4) acc += g_agg[((b << 11) + r) * 64 + c];
    red[t] = acc;
    __syncthreads();
    if (t < 64) ss[t] = (red[t] + red[t + 64] + red[t + 128] + red[t + 192]) * (1.f / 2048.f);
    __syncthreads();
    if (t < 4) {
        float a = 0.f;
        for (int cc = 0; cc < 64; cc++) a += ss[cc] * se_w1[cc * 4 + t];
        rr[t] = fmaxf(a, 0.f);
    }
    __syncthreads();
    if (t < 64) {
        float a = 0.f;
#pragma unroll
        for (int j = 0; j < 4; j++) a += rr[j] * se_w2[j * 64 + t];
        g_y[b * 64 + t] = 1.f / (1.f + expf(-a));
    }
}

// ---------------- K4: per-row avg & max of x_se = agg*y ----------------
__global__ void __launch_bounds__(256) k_rowred() {
    int t = threadIdx.x;
    int w = t >> 5, lane = t & 31;
    int row = blockIdx.x * 8 + w;
    int b = row >> 11;
    float v1 = g_agg[row * 64 + lane] * g_y[b * 64 + lane];
    float v2 = g_agg[row * 64 + 32 + lane] * g_y[b * 64 + 32 + lane];
    float s = v1 + v2;
    float m = fmaxf(v1, v2);
#pragma unroll
    for (int o = 16; o; o >>= 1) {
        s += __shfl_down_sync(0xffffffffu, s, o);
        m = fmaxf(m, __shfl_down_sync(0xffffffffu, m, o));
    }
    if (!lane) { g_avg[row] = s * (1.f / 64.f); g_mx[row] = m; }
}

// ---------------- K5: conv1d attention + residual output ----------------
__global__ void __launch_bounds__(256) k_final(const float* __restrict__ x,
                                               const float* __restrict__ sa,
                                               float* __restrict__ out) {
    int t = threadIdx.x;
    int row = blockIdx.x * 4 + (t >> 6);
    int c = t & 63;
    int b = row >> 11, i = row & 2047;
    float acc = 0.f;
#pragma unroll
    for (int k = 0; k < 7; k++) {
        int jj = i + k - 3;
        if (jj >= 0 && jj < 2048) {
            int rj = (b << 11) + jj;
            acc += g_avg[rj] * sa[k] + g_mx[rj] * sa[7 + k];
        }
    }
    float att = 1.f / (1.f + expf(-acc));
    out[row * 64 + c] = g_agg[row * 64 + c] * g_y[b * 64 + c] * att + x[row * 64 + c];
}

// ---------------- launch ----------------
extern "C" void kernel_launch(void* const* d_in, const int* in_sizes, int n_in,
                              void* d_out, int out_size) {
    const float* x = (const float*)d_in[0];
    // Locate weights robustly: W1 is the first input (after x) with 8192 elements,
    // remaining params follow in order.
    int wi = -1;
    for (int i = 1; i < n_in; i++) {
        if (in_sizes[i] == 8192) { wi = i; break; }
    }
    if (wi < 0) wi = 3;  // fallback to metadata order
    const float* W1    = (const float*)d_in[wi + 0];
    const float* b1    = (const float*)d_in[wi + 1];
    const float* W2    = (const float*)d_in[wi + 2];
    const float* b2    = (const float*)d_in[wi + 3];
    const float* W3    = (const float*)d_in[wi + 4];
    const float* b3    = (const float*)d_in[wi + 5];
    const float* se_w1 = (const float*)d_in[wi + 6];
    const float* se_w2 = (const float*)d_in[wi + 7];
    const float* sa_w  = (const float*)d_in[wi + 8];
    float* out = (float*)d_out;

    cudaFuncSetAttribute(k_dist, cudaFuncAttributeMaxDynamicSharedMemorySize, 16768 * 4);
    cudaFuncSetAttribute(k_edge, cudaFuncAttributeMaxDynamicSharedMemorySize, 50752 * 4);

    k_prep<<<(BB * NN) / 4, 256>>>(x, W1, b1);
    k_dist<<<dim3(16, 16, 16), 256, 16768 * 4>>>(x);
    k_topk<<<BB * NN, 256>>>();
    k_edge<<<(BB * NN) / 16, 256, 50752 * 4>>>(W2, b2, W3, b3);
    k_se<<<BB, 256>>>(se_w1, se_w2);
    k_rowred<<<(BB * NN) / 8, 256>>>();
    k_final<<<(BB * NN) / 4, 256>>>(x, sa_w, out);
}

// round 5
// speedup vs baseline: 1.0968x; 1.0968x over previous
#include <cuda_runtime.h>
#include <cuda_bf16.h>
#include <math.h>
#include <float.h>

// Problem constants
#define BB 16
#define NN 2048
#define CC 64
#define KK 20

// ---------------- device scratch (no runtime alloc allowed) ----------------
__device__ float g_sq[BB * NN];                 // |x|^2 per point
__device__ float g_u[BB * NN * CC];             // xi@(W1a-W1b)+b1
__device__ float g_v[BB * NN * CC];             // xj@W1b
__device__ float g_dist[(size_t)BB * NN * NN];  // 268MB pairwise distances
__device__ int   g_idx[BB * NN * KK];           // knn indices (global rows)
__device__ float g_agg[BB * NN * CC];           // max over k of MLP
__device__ float g_y[BB * CC];                  // SE gate
__device__ float g_avg[BB * NN];
__device__ float g_mx[BB * NN];

// ---------------- K0: per-point prep: sq, u, v (round-1, known good) -------
__global__ void __launch_bounds__(256) k_prep(const float* __restrict__ x,
                                              const float* __restrict__ W1,
                                              const float* __restrict__ b1) {
    __shared__ float sW[128 * 64];   // 32KB
    __shared__ float sx[4 * 64];
    __shared__ float sred[4 * 64];
    int t = threadIdx.x;
    for (int i = t; i < 128 * 64; i += 256) sW[i] = W1[i];
    int p0 = blockIdx.x * 4;
    for (int i = t; i < 4 * 64; i += 256) sx[i] = x[p0 * 64 + i];
    __syncthreads();
    int p = t >> 6, c = t & 63;
    const float* xv = &sx[p * 64];
    float ua = 0.f, va = 0.f;
#pragma unroll 8
    for (int k = 0; k < 64; k++) {
        float xk = xv[k];
        ua += xk * sW[k * 64 + c];
        va += xk * sW[(64 + k) * 64 + c];
    }
    int row = p0 + p;
    g_u[row * 64 + c] = ua - va + b1[c];
    g_v[row * 64 + c] = va;
    sred[t] = xv[c] * xv[c];
    __syncthreads();
    if (c == 0) {
        float s = 0.f;
        for (int k = 0; k < 64; k++) s += sred[p * 64 + k];
        g_sq[row] = s;
    }
}

// ---------------- K1a: pairwise distance GEMM (ROUND-1, known good) --------
// grid (jt=16, it=16, b=16), 256 threads, 128x128 tile, 8x8 per thread
extern __shared__ float dsm[];
__global__ void __launch_bounds__(256) k_dist(const float* __restrict__ x) {
    float* As = dsm;            // [64][129] layout k-major, padded
    float* Bs = dsm + 8256;
    float* sqi = dsm + 16512;   // 128
    float* sqj = dsm + 16640;   // 128
    int t = threadIdx.x;
    int bz = blockIdx.z;
    int it = blockIdx.y, jt = blockIdx.x;
    int base_i = (bz << 11) + it * 128;
    int base_j = (bz << 11) + jt * 128;

    for (int idx = t; idx < 8192; idx += 256) {
        int r = idx >> 6, c = idx & 63;
        As[c * 129 + r] = x[(base_i + r) * 64 + c];
        Bs[c * 129 + r] = x[(base_j + r) * 64 + c];
    }
    if (t < 128) sqi[t] = g_sq[base_i + t];
    else         sqj[t - 128] = g_sq[base_j + t - 128];
    __syncthreads();

    int tx = t & 15, ty = t >> 4;
    float acc[8][8];
#pragma unroll
    for (int r = 0; r < 8; r++)
#pragma unroll
        for (int s = 0; s < 8; s++) acc[r][s] = 0.f;

#pragma unroll 4
    for (int k = 0; k < 64; k++) {
        float a[8], b[8];
#pragma unroll
        for (int r = 0; r < 8; r++) a[r] = As[k * 129 + ty + r * 16];
#pragma unroll
        for (int s = 0; s < 8; s++) b[s] = Bs[k * 129 + tx + s * 16];
#pragma unroll
        for (int r = 0; r < 8; r++)
#pragma unroll
            for (int s = 0; s < 8; s++) acc[r][s] += a[r] * b[s];
    }

#pragma unroll
    for (int r = 0; r < 8; r++) {
        int il = ty + r * 16;
        float sa = sqi[il];
        size_t rowbase = (size_t)(base_i + il) * 2048 + (size_t)jt * 128;
#pragma unroll
        for (int s = 0; s < 8; s++) {
            int jl = tx + s * 16;
            g_dist[rowbase + jl] = sa + sqj[jl] - 2.f * acc[r][s];
        }
    }
}

// ---------------- K1b: top-K=20 smallest per row (ROUND-1, known good) -----
__global__ void __launch_bounds__(256) k_topk() {
    __shared__ float sd[2048];
    __shared__ float bv[8];
    __shared__ int   bi[8];
    int row = blockIdx.x;
    int t = threadIdx.x;
    int b = row >> 11;
    const float* dr = &g_dist[(size_t)row * 2048];
    for (int j = t; j < 2048; j += 256) sd[j] = dr[j];
    __syncthreads();
    int lane = t & 31, w = t >> 5;
    for (int sel = 0; sel < 20; sel++) {
        float mv = 3.4e38f; int mi = 0x7fffffff;
        for (int j = t; j < 2048; j += 256) {
            float v = sd[j];
            if (v < mv) { mv = v; mi = j; }
        }
#pragma unroll
        for (int o = 16; o; o >>= 1) {
            float ov = __shfl_down_sync(0xffffffffu, mv, o);
            int   oi = __shfl_down_sync(0xffffffffu, mi, o);
            if (ov < mv || (ov == mv && oi < mi)) { mv = ov; mi = oi; }
        }
        if (!lane) { bv[w] = mv; bi[w] = mi; }
        __syncthreads();
        if (!t) {
            float best = bv[0]; int bx = bi[0];
            for (int q = 1; q < 8; q++)
                if (bv[q] < best || (bv[q] == best && bi[q] < bx)) { best = bv[q]; bx = bi[q]; }
            sd[bx] = 3.4e38f;
            g_idx[row * 20 + sel] = (b << 11) + bx;
        }
        __syncthreads();
    }
}

// ---------------- K2: edge MLP (layers 2,3) + max over k  (FAST version) ---
// 4 points/block (80 edges), 256 threads, 5x4 microtile, 3 CTAs/SM.
// Certified equivalent to the round-1 k_edge by rounds 3≡4 (identical error
// with either edge version ⇒ edge output identical given identical inputs).
#define EP 81
extern __shared__ float esm[];
__global__ void __launch_bounds__(256) k_edge(const float* __restrict__ W2,
                                              const float* __restrict__ b2,
                                              const float* __restrict__ W3,
                                              const float* __restrict__ b3) {
    float* H1T = esm;                  // [64][EP]
    float* H2T = esm + 64 * EP;        // [64][EP]
    float* Wr  = esm + 2 * 64 * EP;    // [64][64], reused for W2 then W3
    float* su  = Wr + 4096;            // 4*64
    float* b2s = su + 256;             // 64
    float* b3s = b2s + 64;             // 64
    int*  sidx = (int*)(b3s + 64);     // 80

    int t = threadIdx.x;
    int base = blockIdx.x * 4;         // global point row base

    for (int i = t; i < 4096; i += 256) Wr[i] = W2[i];
    su[t] = g_u[base * 64 + t];
    if (t < 64) { b2s[t] = b2[t]; b3s[t] = b3[t]; }
    if (t < 80) sidx[t] = g_idx[base * 20 + t];
    __syncthreads();

    // build H1 = relu(u_i + v_j), transposed [c][e]
    for (int idx = t; idx < 5120; idx += 256) {
        int e = idx >> 6, c = idx & 63;
        float val = su[(e / 20) * 64 + c] + g_v[sidx[e] * 64 + c];
        H1T[c * EP + e] = fmaxf(val, 0.f);
    }
    __syncthreads();

    int tm = t >> 4, tn = t & 15;      // tm: 16 edge slots, tn: 16 channel groups
    float acc[5][4];
#pragma unroll
    for (int r = 0; r < 5; r++)
#pragma unroll
        for (int s = 0; s < 4; s++) acc[r][s] = 0.f;

    // GEMM1: H2 = relu(H1 @ W2 + b2)
#pragma unroll 4
    for (int k = 0; k < 64; k++) {
        float a[5];
#pragma unroll
        for (int r = 0; r < 5; r++) a[r] = H1T[k * EP + tm + 16 * r];
        float4 wv = *(const float4*)&Wr[k * 64 + tn * 4];
#pragma unroll
        for (int r = 0; r < 5; r++) {
            acc[r][0] += a[r] * wv.x;
            acc[r][1] += a[r] * wv.y;
            acc[r][2] += a[r] * wv.z;
            acc[r][3] += a[r] * wv.w;
        }
    }
    {
        float4 bb = *(const float4*)&b2s[tn * 4];
        float bv[4] = {bb.x, bb.y, bb.z, bb.w};
#pragma unroll
        for (int s = 0; s < 4; s++) {
            int n = tn * 4 + s;
#pragma unroll
            for (int r = 0; r < 5; r++)
                H2T[n * EP + tm + 16 * r] = fmaxf(acc[r][s] + bv[s], 0.f);
        }
    }
    __syncthreads();
    for (int i = t; i < 4096; i += 256) Wr[i] = W3[i];
#pragma unroll
    for (int r = 0; r < 5; r++)
#pragma unroll
        for (int s = 0; s < 4; s++) acc[r][s] = 0.f;
    __syncthreads();

    // GEMM2: H3 = H2 @ W3 + b3 (into H1T)
#pragma unroll 4
    for (int k = 0; k < 64; k++) {
        float a[5];
#pragma unroll
        for (int r = 0; r < 5; r++) a[r] = H2T[k * EP + tm + 16 * r];
        float4 wv = *(const float4*)&Wr[k * 64 + tn * 4];
#pragma unroll
        for (int r = 0; r < 5; r++) {
            acc[r][0] += a[r] * wv.x;
            acc[r][1] += a[r] * wv.y;
            acc[r][2] += a[r] * wv.z;
            acc[r][3] += a[r] * wv.w;
        }
    }
    {
        float4 bb = *(const float4*)&b3s[tn * 4];
        float bv[4] = {bb.x, bb.y, bb.z, bb.w};
#pragma unroll
        for (int s = 0; s < 4; s++) {
            int n = tn * 4 + s;
#pragma unroll
            for (int r = 0; r < 5; r++)
                H1T[n * EP + tm + 16 * r] = acc[r][s] + bv[s];
        }
    }
    __syncthreads();

    // max over K=20 per point (4 pts x 64 ch = 256 = one per thread)
    {
        int p = t >> 6, n = t & 63;
        const float* hp = &H1T[n * EP + p * 20];
        float m = hp[0];
#pragma unroll
        for (int kk = 1; kk < 20; kk++) m = fmaxf(m, hp[kk]);
        g_agg[(base + p) * 64 + n] = m;
    }
}

// ---------------- K3: SE gate ----------------
__global__ void __launch_bounds__(256) k_se(const float* __restrict__ se_w1,
                                            const float* __restrict__ se_w2) {
    int b = blockIdx.x, t = threadIdx.x;
    __shared__ float red[256];
    __shared__ float ss[64];
    __shared__ float rr[4];
    int c = t & 63, g = t >> 6;
    float acc = 0.f;
    for (int r = g; r < 2048; r += 4) acc += g_agg[((b << 11) + r) * 64 + c];
    red[t] = acc;
    __syncthreads();
    if (t < 64) ss[t] = (red[t] + red[t + 64] + red[t + 128] + red[t + 192]) * (1.f / 2048.f);
    __syncthreads();
    if (t < 4) {
        float a = 0.f;
        for (int cc = 0; cc < 64; cc++) a += ss[cc] * se_w1[cc * 4 + t];
        rr[t] = fmaxf(a, 0.f);
    }
    __syncthreads();
    if (t < 64) {
        float a = 0.f;
#pragma unroll
        for (int j = 0; j < 4; j++) a += rr[j] * se_w2[j * 64 + t];
        g_y[b * 64 + t] = 1.f / (1.f + expf(-a));
    }
}

// ---------------- K4: per-row avg & max of x_se = agg*y ----------------
__global__ void __launch_bounds__(256) k_rowred() {
    int t = threadIdx.x;
    int w = t >> 5, lane = t & 31;
    int row = blockIdx.x * 8 + w;
    int b = row >> 11;
    float v1 = g_agg[row * 64 + lane] * g_y[b * 64 + lane];
    float v2 = g_agg[row * 64 + 32 + lane] * g_y[b * 64 + 32 + lane];
    float s = v1 + v2;
    float m = fmaxf(v1, v2);
#pragma unroll
    for (int o = 16; o; o >>= 1) {
        s += __shfl_down_sync(0xffffffffu, s, o);
        m = fmaxf(m, __shfl_down_sync(0xffffffffu, m, o));
    }
    if (!lane) { g_avg[row] = s * (1.f / 64.f); g_mx[row] = m; }
}

// ---------------- K5: conv1d attention + residual output ----------------
__global__ void __launch_bounds__(256) k_final(const float* __restrict__ x,
                                               const float* __restrict__ sa,
                                               float* __restrict__ out) {
    int t = threadIdx.x;
    int row = blockIdx.x * 4 + (t >> 6);
    int c = t & 63;
    int b = row >> 11, i = row & 2047;
    float acc = 0.f;
#pragma unroll
    for (int k = 0; k < 7; k++) {
        int jj = i + k - 3;
        if (jj >= 0 && jj < 2048) {
            int rj = (b << 11) + jj;
            acc += g_avg[rj] * sa[k] + g_mx[rj] * sa[7 + k];
        }
    }
    float att = 1.f / (1.f + expf(-acc));
    out[row * 64 + c] = g_agg[row * 64 + c] * g_y[b * 64 + c] * att + x[row * 64 + c];
}

// ---------------- launch ----------------
extern "C" void kernel_launch(void* const* d_in, const int* in_sizes, int n_in,
                              void* d_out, int out_size) {
    const float* x = (const float*)d_in[0];
    int wi = -1;
    for (int i = 1; i < n_in; i++) {
        if (in_sizes[i] == 8192) { wi = i; break; }
    }
    if (wi < 0) wi = 3;
    const float* W1    = (const float*)d_in[wi + 0];
    const float* b1    = (const float*)d_in[wi + 1];
    const float* W2    = (const float*)d_in[wi + 2];
    const float* b2    = (const float*)d_in[wi + 3];
    const float* W3    = (const float*)d_in[wi + 4];
    const float* b3    = (const float*)d_in[wi + 5];
    const float* se_w1 = (const float*)d_in[wi + 6];
    const float* se_w2 = (const float*)d_in[wi + 7];
    const float* sa_w  = (const float*)d_in[wi + 8];
    float* out = (float*)d_out;

    cudaFuncSetAttribute(k_dist, cudaFuncAttributeMaxDynamicSharedMemorySize, 16768 * 4);
    cudaFuncSetAttribute(k_edge, cudaFuncAttributeMaxDynamicSharedMemorySize, 14928 * 4);

    k_prep<<<(BB * NN) / 4, 256>>>(x, W1, b1);
    k_dist<<<dim3(16, 16, 16), 256, 16768 * 4>>>(x);
    k_topk<<<BB * NN, 256>>>();
    k_edge<<<(BB * NN) / 4, 256, 14928 * 4>>>(W2, b2, W3, b3);
    k_se<<<BB, 256>>>(se_w1, se_w2);
    k_rowred<<<(BB * NN) / 8, 256>>>();
    k_final<<<(BB * NN) / 4, 256>>>(x, sa_w, out);
}